// round 2
// baseline (speedup 1.0000x reference)
#include <cuda_runtime.h>
#include <math.h>

// ---------------- problem constants ----------------
#define NB     8
#define CIN    512
#define HH     64
#define WW     64
#define NPOS   4096              // 64*64
#define NA     9
#define NANCH  36864             // 4096*9
#define NSORT  65536             // padded per-image sort length
#define NPRE   3000
#define NPOST  600
#define WPR    47                // words per NMS mask row: ceil(3008/64)

// output layout (floats)
#define OFF_LOCS   ((size_t)0)
#define OFF_SCORES ((size_t)(NB*NANCH*4))                      // 1,179,648
#define OFF_ROIS   (OFF_SCORES + (size_t)(NB*NANCH*2))         // 1,769,472
#define OFF_RIDX   (OFF_ROIS + (size_t)(NB*NPOST*4))           // 1,788,672
#define OFF_ANCH   (OFF_RIDX + (size_t)(NB*NPOST))             // 1,793,472

// ---------------- static scratch ----------------
__device__ float               g_feat[(size_t)NB*CIN*NPOS];        // 64 MiB
__device__ float4              g_roi[(size_t)NB*NANCH];            // clipped rois
__device__ unsigned long long  g_keys[(size_t)NB*NSORT];           // sort keys
__device__ float4              g_topbox[(size_t)NB*3008];
__device__ unsigned long long  g_vmask[(size_t)NB*WPR];
__device__ unsigned long long  g_mask[(size_t)NB*NPRE*WPR];        // 9 MiB

// ---------------- conv 3x3 + relu ----------------
// grid (16 spatial tiles, 8 oc-groups, 8 batch), 256 threads.
// Two-level accumulation: 72-term chunks (8 ic x 9 taps) folded into master
// accumulators -> summation error ~3.6e-7 rel instead of ~3e-6 sequential.
__global__ void __launch_bounds__(256) conv3x3_relu(
    const float* __restrict__ x, const float* __restrict__ w,
    const float* __restrict__ bias)
{
    __shared__ float xs[8][18][18];
    __shared__ float ws[72][64];
    const int tile = blockIdx.x;
    const int oc0  = blockIdx.y * 64;
    const int n    = blockIdx.z;
    const int tx0  = (tile & 3) * 16, ty0 = (tile >> 2) * 16;
    const int t    = threadIdx.x;
    const int px   = t & 15, py = t >> 4;

    float acc[64];
    float accc[64];
#pragma unroll
    for (int i = 0; i < 64; ++i) acc[i] = 0.f;

#pragma unroll 1
    for (int ic0 = 0; ic0 < CIN; ic0 += 8) {
        __syncthreads();
        for (int i = t; i < 8*18*18; i += 256) {
            int ic = i / 324, r = i % 324, yy = r / 18, xx = r % 18;
            int gy = ty0 + yy - 1, gx = tx0 + xx - 1;
            float v = 0.f;
            if ((unsigned)gy < 64u && (unsigned)gx < 64u)
                v = x[(((size_t)n*CIN + ic0 + ic) << 12) + (gy << 6) + gx];
            xs[ic][yy][xx] = v;
        }
        for (int i = t; i < 4608; i += 256) {
            int oc = i & 63, r = i >> 6, ic = r / 9, kk = r % 9;
            ws[ic*9 + kk][oc] = w[(((size_t)(oc0+oc)*CIN) + (ic0+ic))*9 + kk];
        }
        __syncthreads();
#pragma unroll
        for (int i = 0; i < 64; ++i) accc[i] = 0.f;
#pragma unroll 1
        for (int ic = 0; ic < 8; ++ic) {
#pragma unroll
            for (int kk = 0; kk < 9; ++kk) {
                float xv = xs[ic][py + kk/3][px + kk%3];
                const float4* wr = reinterpret_cast<const float4*>(&ws[ic*9+kk][0]);
#pragma unroll
                for (int o = 0; o < 16; ++o) {
                    float4 wv = wr[o];
                    accc[o*4+0] += xv*wv.x; accc[o*4+1] += xv*wv.y;
                    accc[o*4+2] += xv*wv.z; accc[o*4+3] += xv*wv.w;
                }
            }
        }
#pragma unroll
        for (int i = 0; i < 64; ++i) acc[i] += accc[i];
    }
    const int gy = ty0 + py, gx = tx0 + px;
#pragma unroll
    for (int o = 0; o < 64; ++o) {
        float v = acc[o] + __ldg(&bias[oc0 + o]);
        g_feat[(((size_t)n*CIN + oc0 + o) << 12) + (gy << 6) + gx] = fmaxf(v, 0.f);
    }
}

// ---------------- heads (1x1 convs) + proposal prep ----------------
// grid (16 pos-chunks, 8 batch), 256 threads; one thread = one position.
// Chunked accumulation (32-ic folds) + correctly-rounded exp (double).
__global__ void __launch_bounds__(256) heads_proposal(
    const float* __restrict__ sw, const float* __restrict__ sb,
    const float* __restrict__ lw, const float* __restrict__ lb,
    const int* __restrict__ imh, const int* __restrict__ imw,
    float* __restrict__ out)
{
    __shared__ float ws[128][56];
    __shared__ float s_pw[9], s_ph[9];
    const int n = blockIdx.y;
    const int p = blockIdx.x * 256 + threadIdx.x;

    float acc[56];
    float accb[56];
#pragma unroll
    for (int i = 0; i < 56; ++i) acc[i] = 0.f;

    if (threadIdx.x < 9) {
        int a = threadIdx.x;
        double r = (a/3 == 0) ? 0.5 : ((a/3 == 1) ? 1.0 : 2.0);
        double s = (a%3 == 0) ? 8.0 : ((a%3 == 1) ? 16.0 : 32.0);
        double hh = (16.0 * s) * sqrt(r);
        double wd = (16.0 * s) * sqrt(1.0 / r);
        s_pw[a] = (float)(wd / 2.0);
        s_ph[a] = (float)(hh / 2.0);
    }

#pragma unroll 1
    for (int c0 = 0; c0 < CIN; c0 += 128) {
        __syncthreads();
        for (int idx = threadIdx.x; idx < 54*128; idx += 256) {
            int c = idx >> 7, ic = idx & 127;
            ws[ic][c] = (c < 18) ? sw[c*CIN + c0 + ic] : lw[(c-18)*CIN + c0 + ic];
        }
        __syncthreads();
#pragma unroll 1
        for (int icb = 0; icb < 4; ++icb) {
#pragma unroll
            for (int i = 0; i < 56; ++i) accb[i] = 0.f;
#pragma unroll 1
            for (int ic2 = 0; ic2 < 32; ++ic2) {
                int ic = icb*32 + ic2;
                float fv = __ldg(&g_feat[(((size_t)n*CIN + c0 + ic) << 12) + p]);
                const float4* wr = reinterpret_cast<const float4*>(&ws[ic][0]);
#pragma unroll
                for (int q = 0; q < 14; ++q) {
                    float4 wv = wr[q];
                    accb[q*4+0] += fv*wv.x; accb[q*4+1] += fv*wv.y;
                    accb[q*4+2] += fv*wv.z; accb[q*4+3] += fv*wv.w;
                }
            }
#pragma unroll
            for (int i = 0; i < 56; ++i) acc[i] += accb[i];
        }
    }
    __syncthreads();

    // img dims: handle int32 / float32 robustly
    int ihv = imh[0], iwv = imw[0];
    float ihf = (ihv > 0 && ihv < 100000) ? (float)ihv : __int_as_float(ihv);
    float iwf = (iwv > 0 && iwv < 100000) ? (float)iwv : __int_as_float(iwv);

    const int yq = p >> 6, xq = p & 63;
    const float sxf = (float)(xq * 16), syf = (float)(yq * 16);

#pragma unroll 1
    for (int a = 0; a < NA; ++a) {
        size_t j = (size_t)p * NA + a;
        float s0 = acc[2*a]   + __ldg(&sb[2*a]);
        float s1 = acc[2*a+1] + __ldg(&sb[2*a+1]);
        out[OFF_SCORES + ((size_t)n*NANCH + j)*2 + 0] = s0;
        out[OFF_SCORES + ((size_t)n*NANCH + j)*2 + 1] = s1;
        float m  = fmaxf(s0, s1);
        // correctly-rounded exp via double; replicate the fp32 op chain of
        // jax.nn.softmax: exp(x-max) -> f32, sum -> f32, div -> f32
        float e0 = (float)exp((double)(s0 - m));
        float e1 = (float)exp((double)(s1 - m));
        float fg = e1 / (e0 + e1);

        float dx = acc[18 + 4*a + 0] + __ldg(&lb[4*a + 0]);
        float dy = acc[18 + 4*a + 1] + __ldg(&lb[4*a + 1]);
        float dw = acc[18 + 4*a + 2] + __ldg(&lb[4*a + 2]);
        float dh = acc[18 + 4*a + 3] + __ldg(&lb[4*a + 3]);
        out[OFF_LOCS + ((size_t)n*NANCH + j)*4 + 0] = dx;
        out[OFF_LOCS + ((size_t)n*NANCH + j)*4 + 1] = dy;
        out[OFF_LOCS + ((size_t)n*NANCH + j)*4 + 2] = dw;
        out[OFF_LOCS + ((size_t)n*NANCH + j)*4 + 3] = dh;

        float pw = s_pw[a], ph = s_ph[a];
        float ax1 = sxf - pw, ay1 = syf - ph;
        float ax2 = sxf + pw, ay2 = syf + ph;
        if (n == 0) {
            out[OFF_ANCH + j*4 + 0] = ax1;
            out[OFF_ANCH + j*4 + 1] = ay1;
            out[OFF_ANCH + j*4 + 2] = ax2;
            out[OFF_ANCH + j*4 + 3] = ay2;
        }
        float aw  = ax2 - ax1, ah = ay2 - ay1;
        float acx = ax1 + 0.5f*aw, acy = ay1 + 0.5f*ah;
        float cx  = dx*aw + acx, cy = dy*ah + acy;
        float ew  = (float)exp((double)dw);
        float eh  = (float)exp((double)dh);
        float bw  = ew*aw, bh = eh*ah;
        float x1 = cx - 0.5f*bw, x2 = cx + 0.5f*bw;
        float y1 = cy - 0.5f*bh, y2 = cy + 0.5f*bh;
        x1 = fminf(fmaxf(x1, 0.f), iwf); x2 = fminf(fmaxf(x2, 0.f), iwf);
        y1 = fminf(fmaxf(y1, 0.f), ihf); y2 = fminf(fmaxf(y2, 0.f), ihf);
        bool valid = (x2 - x1 >= 16.f) && (y2 - y1 >= 16.f);
        g_roi[(size_t)n*NANCH + j] = make_float4(x1, y1, x2, y2);
        unsigned int sk = valid ? (__float_as_uint(fg) | 0x80000000u) : 0x007FFFFFu;
        g_keys[((size_t)n << 16) + j] =
            ((unsigned long long)sk << 32) | (unsigned long long)(0xFFFFFFFFu - (unsigned int)j);
    }
}

// ---------------- sorting (bitonic, descending, 64-bit keys) ----------------
__global__ void pad_keys() {
    int t = blockIdx.x * blockDim.x + threadIdx.x;          // 8*28672
    if (t >= NB * (NSORT - NANCH)) return;
    int n = t / (NSORT - NANCH);
    int j = NANCH + t % (NSORT - NANCH);
    g_keys[((size_t)n << 16) + j] = 0ull;
}

__global__ void __launch_bounds__(256) sort_local_full() {
    __shared__ unsigned long long s[4096];
    const int base = blockIdx.x * 4096;
    const int seg  = base & (NSORT - 1);
    for (int i = threadIdx.x; i < 4096; i += 256) s[i] = g_keys[base + i];
    __syncthreads();
    for (int k = 2; k <= 4096; k <<= 1) {
        for (int j = k >> 1; j > 0; j >>= 1) {
            for (int t = threadIdx.x; t < 2048; t += 256) {
                int i = ((t & ~(j-1)) << 1) | (t & (j-1));
                bool desc = (((seg + i) & k) == 0);
                unsigned long long a = s[i], b = s[i | j];
                if ((a < b) == desc) { s[i] = b; s[i | j] = a; }
            }
            __syncthreads();
        }
    }
    for (int i = threadIdx.x; i < 4096; i += 256) g_keys[base + i] = s[i];
}

__global__ void sort_global_step(int k, int j) {
    int t = blockIdx.x * blockDim.x + threadIdx.x;          // 8 * 32768
    int img = t >> 15, ti = t & 32767;
    int i = ((ti & ~(j-1)) << 1) | (ti & (j-1));
    bool desc = ((i & k) == 0);
    size_t p = ((size_t)img << 16) + i;
    unsigned long long a = g_keys[p], b = g_keys[p + j];
    if ((a < b) == desc) { g_keys[p] = b; g_keys[p + j] = a; }
}

__global__ void __launch_bounds__(256) sort_local_finish(int k) {
    __shared__ unsigned long long s[4096];
    const int base = blockIdx.x * 4096;
    const int seg  = base & (NSORT - 1);
    for (int i = threadIdx.x; i < 4096; i += 256) s[i] = g_keys[base + i];
    __syncthreads();
    for (int j = 2048; j > 0; j >>= 1) {
        for (int t = threadIdx.x; t < 2048; t += 256) {
            int i = ((t & ~(j-1)) << 1) | (t & (j-1));
            bool desc = (((seg + i) & k) == 0);
            unsigned long long a = s[i], b = s[i | j];
            if ((a < b) == desc) { s[i] = b; s[i | j] = a; }
        }
        __syncthreads();
    }
    for (int i = threadIdx.x; i < 4096; i += 256) g_keys[base + i] = s[i];
}

// ---------------- NMS ----------------
__global__ void gather_top() {
    const int n = blockIdx.x;
    __shared__ unsigned char sval[3008];
    for (int i = threadIdx.x; i < 3008; i += 128) {
        unsigned long long kk = g_keys[((size_t)n << 16) + i];
        unsigned int sk = (unsigned int)(kk >> 32);
        bool valid = (i < NPRE) && (sk > 0x007FFFFFu);
        float4 bx = make_float4(0.f, 0.f, 0.f, 0.f);
        if (valid) {
            unsigned int j = 0xFFFFFFFFu - (unsigned int)kk;
            bx = g_roi[(size_t)n*NANCH + j];
        }
        g_topbox[(size_t)n*3008 + i] = bx;
        sval[i] = valid ? 1 : 0;
    }
    __syncthreads();
    for (int w = threadIdx.x; w < WPR; w += 128) {
        unsigned long long m = 0ull;
        for (int b = 0; b < 64; ++b) {
            int i = w*64 + b;
            if (i < 3008 && sval[i]) m |= (1ull << b);
        }
        g_vmask[(size_t)n*WPR + w] = m;
    }
}

__global__ void __launch_bounds__(256) build_mask() {
    __shared__ float4 sb[NPRE];
    const int n  = blockIdx.y;
    const int r0 = blockIdx.x * 64;
    for (int i = threadIdx.x; i < NPRE; i += 256) sb[i] = g_topbox[(size_t)n*3008 + i];
    __syncthreads();
    for (int t = threadIdx.x; t < 64*WPR; t += 256) {
        int r = r0 + t / WPR;
        int wj = t % WPR;
        if (r >= NPRE) continue;
        float4 a = sb[r];
        float ar = (a.z - a.x) * (a.w - a.y);
        unsigned long long m = 0ull;
#pragma unroll 4
        for (int b = 0; b < 64; ++b) {
            int j = wj*64 + b;
            if (j >= NPRE || j <= r) continue;
            float4 c = sb[j];
            float xx1 = fmaxf(a.x, c.x), yy1 = fmaxf(a.y, c.y);
            float xx2 = fminf(a.z, c.z), yy2 = fminf(a.w, c.w);
            float inter = fmaxf(xx2 - xx1, 0.f) * fmaxf(yy2 - yy1, 0.f);
            float ac = (c.z - c.x) * (c.w - c.y);
            float iou = inter / (ar + ac - inter + 1e-10f);
            if (iou > 0.7f) m |= (1ull << b);
        }
        g_mask[((size_t)n*NPRE + r)*WPR + wj] = m;
    }
}

// one warp per image; writes kept rois (score order) to out + zero-fill.
__global__ void __launch_bounds__(32) nms_scan(float* __restrict__ out) {
    const int n = blockIdx.x;
    const int lane = threadIdx.x;
    __shared__ unsigned long long srow[64*WPR];
    unsigned long long R0 = ~g_vmask[(size_t)n*WPR + lane];
    unsigned long long R1 = (lane < 15) ? ~g_vmask[(size_t)n*WPR + 32 + lane] : ~0ull;
    int cnt = 0;
    const unsigned long long* mbase = &g_mask[(size_t)n*NPRE*WPR];
    const float* tb = (const float*)g_topbox;
    float* orow = out + OFF_ROIS + (size_t)n*NPOST*4;

    for (int c = 0; c < 47; ++c) {
        int r0 = c * 64;
        int nr = min(64, NPRE - r0);
        for (int idx = lane; idx < nr*WPR; idx += 32)
            srow[idx] = mbase[(size_t)r0*WPR + idx];
        __syncwarp();
        for (int ii = 0; ii < nr; ++ii) {
            int i = r0 + ii;
            unsigned long long m0 = srow[ii*WPR + lane];
            unsigned long long m1 = (lane < 15) ? srow[ii*WPR + 32 + lane] : 0ull;
            int w = i >> 6, b = i & 63;
            unsigned long long own = (w < 32) ? R0 : R1;
            unsigned long long v = __shfl_sync(0xFFFFFFFFu, own, w & 31);
            if (!((v >> b) & 1ull)) {
                R0 |= m0; R1 |= m1;
                if (cnt < NPOST && lane < 4)
                    orow[(size_t)cnt*4 + lane] = tb[((size_t)n*3008 + i)*4 + lane];
                ++cnt;
            }
        }
        __syncwarp();
    }
    for (int z = cnt*4 + lane; z < NPOST*4; z += 32) orow[z] = 0.f;
}

__global__ void write_misc(float* __restrict__ out) {
    int i = blockIdx.x * blockDim.x + threadIdx.x;
    if (i < NB * NPOST) out[OFF_RIDX + i] = (float)(i / NPOST);
}

// ---------------- launch ----------------
extern "C" void kernel_launch(void* const* d_in, const int* in_sizes, int n_in,
                              void* d_out, int out_size)
{
    const float* x   = (const float*)d_in[0];
    const int*   imh = (const int*)d_in[1];
    const int*   imw = (const int*)d_in[2];
    const float* w1  = (const float*)d_in[3];
    const float* b1  = (const float*)d_in[4];
    const float* sw  = (const float*)d_in[5];
    const float* sbp = (const float*)d_in[6];
    const float* lw  = (const float*)d_in[7];
    const float* lbp = (const float*)d_in[8];
    float* out = (float*)d_out;

    conv3x3_relu<<<dim3(16, 8, 8), 256>>>(x, w1, b1);
    heads_proposal<<<dim3(16, 8), 256>>>(sw, sbp, lw, lbp, imh, imw, out);
    pad_keys<<<(NB*(NSORT-NANCH) + 255)/256, 256>>>();
    sort_local_full<<<128, 256>>>();
    for (int k = 8192; k <= 65536; k <<= 1) {
        for (int j = k >> 1; j >= 4096; j >>= 1)
            sort_global_step<<<1024, 256>>>(k, j);
        sort_local_finish<<<128, 256>>>(k);
    }
    gather_top<<<8, 128>>>();
    build_mask<<<dim3(47, 8), 256>>>();
    nms_scan<<<8, 32>>>(out);
    write_misc<<<19, 256>>>(out);
}

// round 3
// speedup vs baseline: 1.1840x; 1.1840x over previous
#include <cuda_runtime.h>
#include <math.h>

// ---------------- problem constants ----------------
#define NB     8
#define CIN    512
#define HH     64
#define WW     64
#define NPOS   4096              // 64*64
#define NA     9
#define NANCH  36864             // 4096*9
#define NSORT  65536             // padded per-image sort length
#define NPRE   3000
#define NPOST  600
#define WPR    47                // words per NMS mask row: ceil(3008/64)
#define NPAD   66
#define XPLANE (NPAD*NPAD)       // 4356

// output layout (floats)
#define OFF_LOCS   ((size_t)0)
#define OFF_SCORES ((size_t)(NB*NANCH*4))                      // 1,179,648
#define OFF_ROIS   (OFF_SCORES + (size_t)(NB*NANCH*2))         // 1,769,472
#define OFF_RIDX   (OFF_ROIS + (size_t)(NB*NPOST*4))           // 1,788,672
#define OFF_ANCH   (OFF_RIDX + (size_t)(NB*NPOST))             // 1,793,472

// ---------------- static scratch ----------------
__device__ float               g_feat[(size_t)NB*CIN*NPOS];        // 64 MiB
__device__ float               g_xpad[(size_t)NB*CIN*XPLANE];      // 71 MiB padded input
__device__ float               g_wt[(size_t)CIN*9*CIN];            // transposed weights [ic*9+kk][oc]
__device__ float4              g_roi[(size_t)NB*NANCH];            // clipped rois
__device__ unsigned long long  g_keys[(size_t)NB*NSORT];           // sort keys
__device__ float4              g_topbox[(size_t)NB*3008];
__device__ unsigned long long  g_vmask[(size_t)NB*WPR];
__device__ unsigned long long  g_mask[(size_t)NB*NPRE*WPR];        // 9 MiB

// ---------------- cp.async helpers ----------------
__device__ __forceinline__ unsigned int smem_u32(const void* p) {
    return (unsigned int)__cvta_generic_to_shared(p);
}
__device__ __forceinline__ void cpa4(unsigned int dst, const float* src) {
    asm volatile("cp.async.ca.shared.global [%0], [%1], 4;" :: "r"(dst), "l"(src));
}
#define CP_COMMIT() asm volatile("cp.async.commit_group;" ::: "memory")
#define CP_WAIT(n)  asm volatile("cp.async.wait_group %0;" :: "n"(n) : "memory")

// ---------------- prep: pad input, transpose weights ----------------
__global__ void pad_input(const float* __restrict__ x) {
    long long i = (long long)blockIdx.x * blockDim.x + threadIdx.x;
    if (i >= (long long)NB*CIN*XPLANE) return;
    int pos = (int)(i % XPLANE);
    long long plane = i / XPLANE;                  // n*CIN+ic
    int yy = pos / NPAD, xx = pos - yy*NPAD;
    float v = 0.f;
    if (yy >= 1 && yy <= 64 && xx >= 1 && xx <= 64)
        v = x[(plane << 12) + ((yy-1) << 6) + (xx-1)];
    g_xpad[i] = v;
}

__global__ void transpose_w(const float* __restrict__ w) {
    int i = blockIdx.x * blockDim.x + threadIdx.x;   // CIN*9*CIN = 2359296
    if (i >= CIN*9*CIN) return;
    int oc = i & 511;
    int row = i >> 9;                                 // ic*9+kk
    int ic = row / 9, kk = row - ic*9;
    g_wt[i] = w[((size_t)oc*CIN + ic)*9 + kk];
}

// ---------------- conv 3x3 + relu ----------------
// grid (16 spatial tiles, 8 oc-groups, 8 batch), 256 threads.
// cp.async double-buffered; chunked accumulation identical to passing round
// (8-ic x 9-tap folds) so numerics are bit-identical.
#define XS_ELEMS 2592     // 8*18*18
#define WS_ELEMS 4608     // 72*64
__global__ void __launch_bounds__(256, 1) conv3x3_relu(
    const float* __restrict__ bias)
{
    extern __shared__ float smem[];
    float* xs = smem;                       // [2][2592]
    float* ws = smem + 2*XS_ELEMS;          // [2][4608]
    const int tile = blockIdx.x;
    const int oc0  = blockIdx.y * 64;
    const int n    = blockIdx.z;
    const int tx0  = (tile & 3) * 16, ty0 = (tile >> 2) * 16;
    const int t    = threadIdx.x;
    const int px   = t & 15, py = t >> 4;

    const float* xbase = &g_xpad[((size_t)n*CIN) * XPLANE + (size_t)ty0*NPAD + tx0];
    const unsigned int xs_a = smem_u32(xs);
    const unsigned int ws_a = smem_u32(ws);

    float acc[64];
#pragma unroll
    for (int i = 0; i < 64; ++i) acc[i] = 0.f;

    // issue loads for chunk c into buffer b
    auto issue = [&](int c, int b) {
        const int ic0 = c * 8;
        unsigned int xd = xs_a + (unsigned)b * (XS_ELEMS*4);
        const float* xsrc = xbase + (size_t)ic0 * XPLANE;
#pragma unroll 1
        for (int i = t; i < XS_ELEMS; i += 256) {
            int ic = i / 324, r = i - ic*324;
            int yy = r / 18, xx = r - yy*18;
            cpa4(xd + (unsigned)i*4, xsrc + (size_t)ic*XPLANE + yy*NPAD + xx);
        }
        unsigned int wd = ws_a + (unsigned)b * (WS_ELEMS*4);
        const float* wsrc = &g_wt[(size_t)(ic0*9) * CIN + oc0];
#pragma unroll 1
        for (int i = t; i < WS_ELEMS; i += 256) {
            cpa4(wd + (unsigned)i*4, wsrc + (size_t)(i >> 6)*CIN + (i & 63));
        }
        CP_COMMIT();
    };

    issue(0, 0);
#pragma unroll 1
    for (int c = 0; c < 64; ++c) {
        const int b = c & 1;
        if (c < 63) { issue(c + 1, b ^ 1); CP_WAIT(1); }
        else        { CP_WAIT(0); }
        __syncthreads();

        const float* xsb = xs + b * XS_ELEMS;
        const float* wsb = ws + b * WS_ELEMS;
        float accc[64];
#pragma unroll
        for (int i = 0; i < 64; ++i) accc[i] = 0.f;
#pragma unroll 1
        for (int ic = 0; ic < 8; ++ic) {
#pragma unroll
            for (int kk = 0; kk < 9; ++kk) {
                float xv = xsb[ic*324 + (py + kk/3)*18 + px + kk%3];
                const float4* wr = reinterpret_cast<const float4*>(&wsb[(ic*9+kk)*64]);
#pragma unroll
                for (int o = 0; o < 16; ++o) {
                    float4 wv = wr[o];
                    accc[o*4+0] += xv*wv.x; accc[o*4+1] += xv*wv.y;
                    accc[o*4+2] += xv*wv.z; accc[o*4+3] += xv*wv.w;
                }
            }
        }
#pragma unroll
        for (int i = 0; i < 64; ++i) acc[i] += accc[i];
        __syncthreads();   // protect buffer b before it is re-filled at c+1
    }

    const int gy = ty0 + py, gx = tx0 + px;
#pragma unroll
    for (int o = 0; o < 64; ++o) {
        float v = acc[o] + __ldg(&bias[oc0 + o]);
        g_feat[(((size_t)n*CIN + oc0 + o) << 12) + (gy << 6) + gx] = fmaxf(v, 0.f);
    }
}

// ---------------- heads (1x1 convs) + proposal prep ----------------
__global__ void __launch_bounds__(256, 1) heads_proposal(
    const float* __restrict__ sw, const float* __restrict__ sb,
    const float* __restrict__ lw, const float* __restrict__ lb,
    const int* __restrict__ imh, const int* __restrict__ imw,
    float* __restrict__ out)
{
    __shared__ float ws[128][56];
    __shared__ float s_pw[9], s_ph[9];
    const int n = blockIdx.y;
    const int p = blockIdx.x * 256 + threadIdx.x;

    float acc[56];
    float accb[56];
#pragma unroll
    for (int i = 0; i < 56; ++i) acc[i] = 0.f;

    if (threadIdx.x < 9) {
        int a = threadIdx.x;
        double r = (a/3 == 0) ? 0.5 : ((a/3 == 1) ? 1.0 : 2.0);
        double s = (a%3 == 0) ? 8.0 : ((a%3 == 1) ? 16.0 : 32.0);
        double hh = (16.0 * s) * sqrt(r);
        double wd = (16.0 * s) * sqrt(1.0 / r);
        s_pw[a] = (float)(wd / 2.0);
        s_ph[a] = (float)(hh / 2.0);
    }

#pragma unroll 1
    for (int c0 = 0; c0 < CIN; c0 += 128) {
        __syncthreads();
        for (int idx = threadIdx.x; idx < 54*128; idx += 256) {
            int c = idx >> 7, ic = idx & 127;
            ws[ic][c] = (c < 18) ? sw[c*CIN + c0 + ic] : lw[(c-18)*CIN + c0 + ic];
        }
        __syncthreads();
#pragma unroll 1
        for (int icb = 0; icb < 4; ++icb) {
#pragma unroll
            for (int i = 0; i < 56; ++i) accb[i] = 0.f;
#pragma unroll 1
            for (int ic2 = 0; ic2 < 32; ++ic2) {
                int ic = icb*32 + ic2;
                float fv = __ldg(&g_feat[(((size_t)n*CIN + c0 + ic) << 12) + p]);
                const float4* wr = reinterpret_cast<const float4*>(&ws[ic][0]);
#pragma unroll
                for (int q = 0; q < 14; ++q) {
                    float4 wv = wr[q];
                    accb[q*4+0] += fv*wv.x; accb[q*4+1] += fv*wv.y;
                    accb[q*4+2] += fv*wv.z; accb[q*4+3] += fv*wv.w;
                }
            }
#pragma unroll
            for (int i = 0; i < 56; ++i) acc[i] += accb[i];
        }
    }
    __syncthreads();

    int ihv = imh[0], iwv = imw[0];
    float ihf = (ihv > 0 && ihv < 100000) ? (float)ihv : __int_as_float(ihv);
    float iwf = (iwv > 0 && iwv < 100000) ? (float)iwv : __int_as_float(iwv);

    const int yq = p >> 6, xq = p & 63;
    const float sxf = (float)(xq * 16), syf = (float)(yq * 16);

#pragma unroll 1
    for (int a = 0; a < NA; ++a) {
        size_t j = (size_t)p * NA + a;
        float s0 = acc[2*a]   + __ldg(&sb[2*a]);
        float s1 = acc[2*a+1] + __ldg(&sb[2*a+1]);
        out[OFF_SCORES + ((size_t)n*NANCH + j)*2 + 0] = s0;
        out[OFF_SCORES + ((size_t)n*NANCH + j)*2 + 1] = s1;
        float m  = fmaxf(s0, s1);
        float e0 = (float)exp((double)(s0 - m));
        float e1 = (float)exp((double)(s1 - m));
        float fg = e1 / (e0 + e1);

        float dx = acc[18 + 4*a + 0] + __ldg(&lb[4*a + 0]);
        float dy = acc[18 + 4*a + 1] + __ldg(&lb[4*a + 1]);
        float dw = acc[18 + 4*a + 2] + __ldg(&lb[4*a + 2]);
        float dh = acc[18 + 4*a + 3] + __ldg(&lb[4*a + 3]);
        out[OFF_LOCS + ((size_t)n*NANCH + j)*4 + 0] = dx;
        out[OFF_LOCS + ((size_t)n*NANCH + j)*4 + 1] = dy;
        out[OFF_LOCS + ((size_t)n*NANCH + j)*4 + 2] = dw;
        out[OFF_LOCS + ((size_t)n*NANCH + j)*4 + 3] = dh;

        float pw = s_pw[a], ph = s_ph[a];
        float ax1 = sxf - pw, ay1 = syf - ph;
        float ax2 = sxf + pw, ay2 = syf + ph;
        if (n == 0) {
            out[OFF_ANCH + j*4 + 0] = ax1;
            out[OFF_ANCH + j*4 + 1] = ay1;
            out[OFF_ANCH + j*4 + 2] = ax2;
            out[OFF_ANCH + j*4 + 3] = ay2;
        }
        float aw  = ax2 - ax1, ah = ay2 - ay1;
        float acx = ax1 + 0.5f*aw, acy = ay1 + 0.5f*ah;
        float cx  = dx*aw + acx, cy = dy*ah + acy;
        float ew  = (float)exp((double)dw);
        float eh  = (float)exp((double)dh);
        float bw  = ew*aw, bh = eh*ah;
        float x1 = cx - 0.5f*bw, x2 = cx + 0.5f*bw;
        float y1 = cy - 0.5f*bh, y2 = cy + 0.5f*bh;
        x1 = fminf(fmaxf(x1, 0.f), iwf); x2 = fminf(fmaxf(x2, 0.f), iwf);
        y1 = fminf(fmaxf(y1, 0.f), ihf); y2 = fminf(fmaxf(y2, 0.f), ihf);
        bool valid = (x2 - x1 >= 16.f) && (y2 - y1 >= 16.f);
        g_roi[(size_t)n*NANCH + j] = make_float4(x1, y1, x2, y2);
        unsigned int sk = valid ? (__float_as_uint(fg) | 0x80000000u) : 0x007FFFFFu;
        g_keys[((size_t)n << 16) + j] =
            ((unsigned long long)sk << 32) | (unsigned long long)(0xFFFFFFFFu - (unsigned int)j);
    }
}

// ---------------- sorting (bitonic, descending, 64-bit keys) ----------------
__global__ void pad_keys() {
    int t = blockIdx.x * blockDim.x + threadIdx.x;          // 8*28672
    if (t >= NB * (NSORT - NANCH)) return;
    int n = t / (NSORT - NANCH);
    int j = NANCH + t % (NSORT - NANCH);
    g_keys[((size_t)n << 16) + j] = 0ull;
}

__global__ void __launch_bounds__(256) sort_local_full() {
    __shared__ unsigned long long s[4096];
    const int base = blockIdx.x * 4096;
    const int seg  = base & (NSORT - 1);
    for (int i = threadIdx.x; i < 4096; i += 256) s[i] = g_keys[base + i];
    __syncthreads();
    for (int k = 2; k <= 4096; k <<= 1) {
        for (int j = k >> 1; j > 0; j >>= 1) {
            for (int t = threadIdx.x; t < 2048; t += 256) {
                int i = ((t & ~(j-1)) << 1) | (t & (j-1));
                bool desc = (((seg + i) & k) == 0);
                unsigned long long a = s[i], b = s[i | j];
                if ((a < b) == desc) { s[i] = b; s[i | j] = a; }
            }
            __syncthreads();
        }
    }
    for (int i = threadIdx.x; i < 4096; i += 256) g_keys[base + i] = s[i];
}

__global__ void sort_global_step(int k, int j) {
    int t = blockIdx.x * blockDim.x + threadIdx.x;          // 8 * 32768
    int img = t >> 15, ti = t & 32767;
    int i = ((ti & ~(j-1)) << 1) | (ti & (j-1));
    bool desc = ((i & k) == 0);
    size_t p = ((size_t)img << 16) + i;
    unsigned long long a = g_keys[p], b = g_keys[p + j];
    if ((a < b) == desc) { g_keys[p] = b; g_keys[p + j] = a; }
}

__global__ void __launch_bounds__(256) sort_local_finish(int k) {
    __shared__ unsigned long long s[4096];
    const int base = blockIdx.x * 4096;
    const int seg  = base & (NSORT - 1);
    for (int i = threadIdx.x; i < 4096; i += 256) s[i] = g_keys[base + i];
    __syncthreads();
    for (int j = 2048; j > 0; j >>= 1) {
        for (int t = threadIdx.x; t < 2048; t += 256) {
            int i = ((t & ~(j-1)) << 1) | (t & (j-1));
            bool desc = (((seg + i) & k) == 0);
            unsigned long long a = s[i], b = s[i | j];
            if ((a < b) == desc) { s[i] = b; s[i | j] = a; }
        }
        __syncthreads();
    }
    for (int i = threadIdx.x; i < 4096; i += 256) g_keys[base + i] = s[i];
}

// ---------------- NMS ----------------
__global__ void gather_top() {
    const int n = blockIdx.x;
    __shared__ unsigned char sval[3008];
    for (int i = threadIdx.x; i < 3008; i += 128) {
        unsigned long long kk = g_keys[((size_t)n << 16) + i];
        unsigned int sk = (unsigned int)(kk >> 32);
        bool valid = (i < NPRE) && (sk > 0x007FFFFFu);
        float4 bx = make_float4(0.f, 0.f, 0.f, 0.f);
        if (valid) {
            unsigned int j = 0xFFFFFFFFu - (unsigned int)kk;
            bx = g_roi[(size_t)n*NANCH + j];
        }
        g_topbox[(size_t)n*3008 + i] = bx;
        sval[i] = valid ? 1 : 0;
    }
    __syncthreads();
    for (int w = threadIdx.x; w < WPR; w += 128) {
        unsigned long long m = 0ull;
        for (int b = 0; b < 64; ++b) {
            int i = w*64 + b;
            if (i < 3008 && sval[i]) m |= (1ull << b);
        }
        g_vmask[(size_t)n*WPR + w] = m;
    }
}

__global__ void __launch_bounds__(256) build_mask() {
    __shared__ float4 sb[NPRE];
    const int n  = blockIdx.y;
    const int r0 = blockIdx.x * 64;
    for (int i = threadIdx.x; i < NPRE; i += 256) sb[i] = g_topbox[(size_t)n*3008 + i];
    __syncthreads();
    for (int t = threadIdx.x; t < 64*WPR; t += 256) {
        int r = r0 + t / WPR;
        int wj = t % WPR;
        if (r >= NPRE) continue;
        float4 a = sb[r];
        float ar = (a.z - a.x) * (a.w - a.y);
        unsigned long long m = 0ull;
#pragma unroll 4
        for (int b = 0; b < 64; ++b) {
            int j = wj*64 + b;
            if (j >= NPRE || j <= r) continue;
            float4 c = sb[j];
            float xx1 = fmaxf(a.x, c.x), yy1 = fmaxf(a.y, c.y);
            float xx2 = fminf(a.z, c.z), yy2 = fminf(a.w, c.w);
            float inter = fmaxf(xx2 - xx1, 0.f) * fmaxf(yy2 - yy1, 0.f);
            float ac = (c.z - c.x) * (c.w - c.y);
            float iou = inter / (ar + ac - inter + 1e-10f);
            if (iou > 0.7f) m |= (1ull << b);
        }
        g_mask[((size_t)n*NPRE + r)*WPR + wj] = m;
    }
}

__global__ void __launch_bounds__(32) nms_scan(float* __restrict__ out) {
    const int n = blockIdx.x;
    const int lane = threadIdx.x;
    __shared__ unsigned long long srow[64*WPR];
    unsigned long long R0 = ~g_vmask[(size_t)n*WPR + lane];
    unsigned long long R1 = (lane < 15) ? ~g_vmask[(size_t)n*WPR + 32 + lane] : ~0ull;
    int cnt = 0;
    const unsigned long long* mbase = &g_mask[(size_t)n*NPRE*WPR];
    const float* tb = (const float*)g_topbox;
    float* orow = out + OFF_ROIS + (size_t)n*NPOST*4;

    for (int c = 0; c < 47; ++c) {
        int r0 = c * 64;
        int nr = min(64, NPRE - r0);
        for (int idx = lane; idx < nr*WPR; idx += 32)
            srow[idx] = mbase[(size_t)r0*WPR + idx];
        __syncwarp();
        for (int ii = 0; ii < nr; ++ii) {
            int i = r0 + ii;
            unsigned long long m0 = srow[ii*WPR + lane];
            unsigned long long m1 = (lane < 15) ? srow[ii*WPR + 32 + lane] : 0ull;
            int w = i >> 6, b = i & 63;
            unsigned long long own = (w < 32) ? R0 : R1;
            unsigned long long v = __shfl_sync(0xFFFFFFFFu, own, w & 31);
            if (!((v >> b) & 1ull)) {
                R0 |= m0; R1 |= m1;
                if (cnt < NPOST && lane < 4)
                    orow[(size_t)cnt*4 + lane] = tb[((size_t)n*3008 + i)*4 + lane];
                ++cnt;
            }
        }
        __syncwarp();
    }
    for (int z = cnt*4 + lane; z < NPOST*4; z += 32) orow[z] = 0.f;
}

__global__ void write_misc(float* __restrict__ out) {
    int i = blockIdx.x * blockDim.x + threadIdx.x;
    if (i < NB * NPOST) out[OFF_RIDX + i] = (float)(i / NPOST);
}

// diagnostic no-op: shifts launch index so ncu (-s 5 -c 1) profiles the conv
__global__ void noop_k() {}

// ---------------- launch ----------------
extern "C" void kernel_launch(void* const* d_in, const int* in_sizes, int n_in,
                              void* d_out, int out_size)
{
    const float* x   = (const float*)d_in[0];
    const int*   imh = (const int*)d_in[1];
    const int*   imw = (const int*)d_in[2];
    const float* w1  = (const float*)d_in[3];
    const float* b1  = (const float*)d_in[4];
    const float* sw  = (const float*)d_in[5];
    const float* sbp = (const float*)d_in[6];
    const float* lw  = (const float*)d_in[7];
    const float* lbp = (const float*)d_in[8];
    float* out = (float*)d_out;

    static int smem_set = 0;
    if (!smem_set) {
        cudaFuncSetAttribute(conv3x3_relu,
            cudaFuncAttributeMaxDynamicSharedMemorySize, 2*(XS_ELEMS+WS_ELEMS)*4);
        smem_set = 1;
    }

    // 3 prep + 2 noop launches -> conv is launch #6 (ncu -s 5 -c 1 lands on it)
    pad_input<<<(int)(((size_t)NB*CIN*XPLANE + 255)/256), 256>>>(x);
    transpose_w<<<(CIN*9*CIN + 255)/256, 256>>>(w1);
    pad_keys<<<(NB*(NSORT-NANCH) + 255)/256, 256>>>();
    noop_k<<<1, 32>>>();
    noop_k<<<1, 32>>>();

    conv3x3_relu<<<dim3(16, 8, 8), 256, 2*(XS_ELEMS+WS_ELEMS)*4>>>(b1);
    heads_proposal<<<dim3(16, 8), 256>>>(sw, sbp, lw, lbp, imh, imw, out);
    sort_local_full<<<128, 256>>>();
    for (int k = 8192; k <= 65536; k <<= 1) {
        for (int j = k >> 1; j >= 4096; j >>= 1)
            sort_global_step<<<1024, 256>>>(k, j);
        sort_local_finish<<<128, 256>>>(k);
    }
    gather_top<<<8, 128>>>();
    build_mask<<<dim3(47, 8), 256>>>();
    nms_scan<<<8, 32>>>(out);
    write_misc<<<19, 256>>>(out);
}

// round 4
// speedup vs baseline: 1.2333x; 1.0417x over previous
#include <cuda_runtime.h>
#include <math.h>

// ---------------- problem constants ----------------
#define NB     8
#define CIN    512
#define HH     64
#define WW     64
#define NPOS   4096              // 64*64
#define NA     9
#define NANCH  36864             // 4096*9
#define NSORT  65536             // padded per-image sort length
#define NPRE   3000
#define NPOST  600
#define WPR    47                // words per NMS mask row: ceil(3008/64)
#define NPAD   66
#define XPLANE (NPAD*NPAD)       // 4356

// output layout (floats)
#define OFF_LOCS   ((size_t)0)
#define OFF_SCORES ((size_t)(NB*NANCH*4))                      // 1,179,648
#define OFF_ROIS   (OFF_SCORES + (size_t)(NB*NANCH*2))         // 1,769,472
#define OFF_RIDX   (OFF_ROIS + (size_t)(NB*NPOST*4))           // 1,788,672
#define OFF_ANCH   (OFF_RIDX + (size_t)(NB*NPOST))             // 1,793,472

// ---------------- static scratch ----------------
__device__ float               g_feat[(size_t)NB*CIN*NPOS];        // 64 MiB
__device__ float               g_xpad[(size_t)NB*CIN*XPLANE];      // 71 MiB padded input
__device__ float               g_wt[(size_t)CIN*9*CIN];            // transposed weights [ic*9+kk][oc]
__device__ float4              g_roi[(size_t)NB*NANCH];            // clipped rois
__device__ unsigned long long  g_keys[(size_t)NB*NSORT];           // sort keys
__device__ float4              g_topbox[(size_t)NB*3008];
__device__ unsigned long long  g_vmask[(size_t)NB*WPR];
__device__ unsigned long long  g_mask[(size_t)NB*NPRE*WPR];        // 9 MiB

// ---------------- packed f32x2 helpers (Blackwell) ----------------
#define FMA2(d, a, b, c) \
    asm("fma.rn.f32x2 %0, %1, %2, %3;" : "=l"(d) : "l"(a), "l"(b), "l"(c))
#define ADD2(d, a, b) \
    asm("add.rn.f32x2 %0, %1, %2;" : "=l"(d) : "l"(a), "l"(b))
#define PACK2(d, f) \
    asm("mov.b64 %0, {%1, %1};" : "=l"(d) : "f"(f))
#define UNPACK2(lo, hi, v) \
    asm("mov.b64 {%0, %1}, %2;" : "=f"(lo), "=f"(hi) : "l"(v))

// ---------------- cp.async helpers ----------------
__device__ __forceinline__ unsigned int smem_u32(const void* p) {
    return (unsigned int)__cvta_generic_to_shared(p);
}
__device__ __forceinline__ void cpa4(unsigned int dst, const float* src) {
    asm volatile("cp.async.ca.shared.global [%0], [%1], 4;" :: "r"(dst), "l"(src));
}
#define CP_COMMIT() asm volatile("cp.async.commit_group;" ::: "memory")
#define CP_WAIT(n)  asm volatile("cp.async.wait_group %0;" :: "n"(n) : "memory")

// ---------------- prep: pad input, transpose weights ----------------
__global__ void pad_input(const float* __restrict__ x) {
    long long i = (long long)blockIdx.x * blockDim.x + threadIdx.x;
    if (i >= (long long)NB*CIN*XPLANE) return;
    int pos = (int)(i % XPLANE);
    long long plane = i / XPLANE;                  // n*CIN+ic
    int yy = pos / NPAD, xx = pos - yy*NPAD;
    float v = 0.f;
    if (yy >= 1 && yy <= 64 && xx >= 1 && xx <= 64)
        v = x[(plane << 12) + ((yy-1) << 6) + (xx-1)];
    g_xpad[i] = v;
}

__global__ void transpose_w(const float* __restrict__ w) {
    int i = blockIdx.x * blockDim.x + threadIdx.x;   // CIN*9*CIN = 2359296
    if (i >= CIN*9*CIN) return;
    int oc = i & 511;
    int row = i >> 9;                                 // ic*9+kk
    int ic = row / 9, kk = row - ic*9;
    g_wt[i] = w[((size_t)oc*CIN + ic)*9 + kk];
}

// ---------------- conv 3x3 + relu (packed f32x2 math) ----------------
// grid (16 spatial tiles, 8 oc-groups, 8 batch), 256 threads.
// Same accumulation structure as the passing kernel (8-ic x 9-tap chunks
// folded into master) but each pair of adjacent oc lanes rides one FFMA2.
// Per-lane arithmetic order is bit-identical to the scalar version.
#define XS_ELEMS 2592     // 8*18*18
#define WS_ELEMS 4608     // 72*64
__global__ void __launch_bounds__(256, 1) conv3x3_relu(
    const float* __restrict__ bias)
{
    extern __shared__ float smem[];
    float* xs = smem;                       // [2][2592]
    float* ws = smem + 2*XS_ELEMS;          // [2][4608]
    const int tile = blockIdx.x;
    const int oc0  = blockIdx.y * 64;
    const int n    = blockIdx.z;
    const int tx0  = (tile & 3) * 16, ty0 = (tile >> 2) * 16;
    const int t    = threadIdx.x;
    const int px   = t & 15, py = t >> 4;

    const float* xbase = &g_xpad[((size_t)n*CIN) * XPLANE + (size_t)ty0*NPAD + tx0];
    const unsigned int xs_a = smem_u32(xs);
    const unsigned int ws_a = smem_u32(ws);

    unsigned long long acc2[32];
#pragma unroll
    for (int i = 0; i < 32; ++i) acc2[i] = 0ull;

    auto issue = [&](int c, int b) {
        const int ic0 = c * 8;
        unsigned int xd = xs_a + (unsigned)b * (XS_ELEMS*4);
        const float* xsrc = xbase + (size_t)ic0 * XPLANE;
#pragma unroll 1
        for (int i = t; i < XS_ELEMS; i += 256) {
            int ic = i / 324, r = i - ic*324;
            int yy = r / 18, xx = r - yy*18;
            cpa4(xd + (unsigned)i*4, xsrc + (size_t)ic*XPLANE + yy*NPAD + xx);
        }
        unsigned int wd = ws_a + (unsigned)b * (WS_ELEMS*4);
        const float* wsrc = &g_wt[(size_t)(ic0*9) * CIN + oc0];
#pragma unroll 1
        for (int i = t; i < WS_ELEMS; i += 256) {
            cpa4(wd + (unsigned)i*4, wsrc + (size_t)(i >> 6)*CIN + (i & 63));
        }
        CP_COMMIT();
    };

    issue(0, 0);
#pragma unroll 1
    for (int c = 0; c < 64; ++c) {
        const int b = c & 1;
        if (c < 63) { issue(c + 1, b ^ 1); CP_WAIT(1); }
        else        { CP_WAIT(0); }
        __syncthreads();

        const float* xsb = xs + b * XS_ELEMS;
        const float* wsb = ws + b * WS_ELEMS;
        unsigned long long c2[32];
#pragma unroll
        for (int i = 0; i < 32; ++i) c2[i] = 0ull;
#pragma unroll 1
        for (int ic = 0; ic < 8; ++ic) {
#pragma unroll
            for (int kk = 0; kk < 9; ++kk) {
                float xv = xsb[ic*324 + (py + kk/3)*18 + px + kk%3];
                unsigned long long xv2; PACK2(xv2, xv);
                const ulonglong2* wr =
                    reinterpret_cast<const ulonglong2*>(&wsb[(ic*9+kk)*64]);
#pragma unroll
                for (int o = 0; o < 16; ++o) {
                    ulonglong2 wv = wr[o];
                    FMA2(c2[o*2+0], xv2, wv.x, c2[o*2+0]);
                    FMA2(c2[o*2+1], xv2, wv.y, c2[o*2+1]);
                }
            }
        }
#pragma unroll
        for (int i = 0; i < 32; ++i) ADD2(acc2[i], acc2[i], c2[i]);
        __syncthreads();   // protect buffer b before it is re-filled
    }

    const int gy = ty0 + py, gx = tx0 + px;
    float* fout = &g_feat[(((size_t)n*CIN + oc0) << 12) + (gy << 6) + gx];
#pragma unroll
    for (int j = 0; j < 32; ++j) {
        float lo, hi; UNPACK2(lo, hi, acc2[j]);
        float v0 = lo + __ldg(&bias[oc0 + 2*j]);
        float v1 = hi + __ldg(&bias[oc0 + 2*j + 1]);
        fout[((size_t)(2*j)) << 12]   = fmaxf(v0, 0.f);
        fout[((size_t)(2*j+1)) << 12] = fmaxf(v1, 0.f);
    }
}

// ---------------- heads (1x1 convs) + proposal prep ----------------
__global__ void __launch_bounds__(256, 1) heads_proposal(
    const float* __restrict__ sw, const float* __restrict__ sb,
    const float* __restrict__ lw, const float* __restrict__ lb,
    const int* __restrict__ imh, const int* __restrict__ imw,
    float* __restrict__ out)
{
    __shared__ float ws[128][56];
    __shared__ float s_pw[9], s_ph[9];
    const int n = blockIdx.y;
    const int p = blockIdx.x * 256 + threadIdx.x;

    unsigned long long acc2[28], accb2[28];
#pragma unroll
    for (int i = 0; i < 28; ++i) acc2[i] = 0ull;

    if (threadIdx.x < 9) {
        int a = threadIdx.x;
        double r = (a/3 == 0) ? 0.5 : ((a/3 == 1) ? 1.0 : 2.0);
        double s = (a%3 == 0) ? 8.0 : ((a%3 == 1) ? 16.0 : 32.0);
        double hh = (16.0 * s) * sqrt(r);
        double wd = (16.0 * s) * sqrt(1.0 / r);
        s_pw[a] = (float)(wd / 2.0);
        s_ph[a] = (float)(hh / 2.0);
    }

#pragma unroll 1
    for (int c0 = 0; c0 < CIN; c0 += 128) {
        __syncthreads();
        for (int idx = threadIdx.x; idx < 54*128; idx += 256) {
            int c = idx >> 7, ic = idx & 127;
            ws[ic][c] = (c < 18) ? sw[c*CIN + c0 + ic] : lw[(c-18)*CIN + c0 + ic];
        }
        __syncthreads();
#pragma unroll 1
        for (int icb = 0; icb < 4; ++icb) {
#pragma unroll
            for (int i = 0; i < 28; ++i) accb2[i] = 0ull;
#pragma unroll 1
            for (int ic2 = 0; ic2 < 32; ++ic2) {
                int ic = icb*32 + ic2;
                float fv = __ldg(&g_feat[(((size_t)n*CIN + c0 + ic) << 12) + p]);
                unsigned long long fv2; PACK2(fv2, fv);
                const ulonglong2* wr = reinterpret_cast<const ulonglong2*>(&ws[ic][0]);
#pragma unroll
                for (int q = 0; q < 14; ++q) {
                    ulonglong2 wv = wr[q];
                    FMA2(accb2[q*2+0], fv2, wv.x, accb2[q*2+0]);
                    FMA2(accb2[q*2+1], fv2, wv.y, accb2[q*2+1]);
                }
            }
#pragma unroll
            for (int i = 0; i < 28; ++i) ADD2(acc2[i], acc2[i], accb2[i]);
        }
    }
    __syncthreads();

    float acc[56];
#pragma unroll
    for (int j = 0; j < 28; ++j) UNPACK2(acc[2*j], acc[2*j+1], acc2[j]);

    int ihv = imh[0], iwv = imw[0];
    float ihf = (ihv > 0 && ihv < 100000) ? (float)ihv : __int_as_float(ihv);
    float iwf = (iwv > 0 && iwv < 100000) ? (float)iwv : __int_as_float(iwv);

    const int yq = p >> 6, xq = p & 63;
    const float sxf = (float)(xq * 16), syf = (float)(yq * 16);

#pragma unroll 1
    for (int a = 0; a < NA; ++a) {
        size_t j = (size_t)p * NA + a;
        float s0 = acc[2*a]   + __ldg(&sb[2*a]);
        float s1 = acc[2*a+1] + __ldg(&sb[2*a+1]);
        out[OFF_SCORES + ((size_t)n*NANCH + j)*2 + 0] = s0;
        out[OFF_SCORES + ((size_t)n*NANCH + j)*2 + 1] = s1;
        float m  = fmaxf(s0, s1);
        float e0 = (float)exp((double)(s0 - m));
        float e1 = (float)exp((double)(s1 - m));
        float fg = e1 / (e0 + e1);

        float dx = acc[18 + 4*a + 0] + __ldg(&lb[4*a + 0]);
        float dy = acc[18 + 4*a + 1] + __ldg(&lb[4*a + 1]);
        float dw = acc[18 + 4*a + 2] + __ldg(&lb[4*a + 2]);
        float dh = acc[18 + 4*a + 3] + __ldg(&lb[4*a + 3]);
        out[OFF_LOCS + ((size_t)n*NANCH + j)*4 + 0] = dx;
        out[OFF_LOCS + ((size_t)n*NANCH + j)*4 + 1] = dy;
        out[OFF_LOCS + ((size_t)n*NANCH + j)*4 + 2] = dw;
        out[OFF_LOCS + ((size_t)n*NANCH + j)*4 + 3] = dh;

        float pw = s_pw[a], ph = s_ph[a];
        float ax1 = sxf - pw, ay1 = syf - ph;
        float ax2 = sxf + pw, ay2 = syf + ph;
        if (n == 0) {
            out[OFF_ANCH + j*4 + 0] = ax1;
            out[OFF_ANCH + j*4 + 1] = ay1;
            out[OFF_ANCH + j*4 + 2] = ax2;
            out[OFF_ANCH + j*4 + 3] = ay2;
        }
        float aw  = ax2 - ax1, ah = ay2 - ay1;
        float acx = ax1 + 0.5f*aw, acy = ay1 + 0.5f*ah;
        float cx  = dx*aw + acx, cy = dy*ah + acy;
        float ew  = (float)exp((double)dw);
        float eh  = (float)exp((double)dh);
        float bw  = ew*aw, bh = eh*ah;
        float x1 = cx - 0.5f*bw, x2 = cx + 0.5f*bw;
        float y1 = cy - 0.5f*bh, y2 = cy + 0.5f*bh;
        x1 = fminf(fmaxf(x1, 0.f), iwf); x2 = fminf(fmaxf(x2, 0.f), iwf);
        y1 = fminf(fmaxf(y1, 0.f), ihf); y2 = fminf(fmaxf(y2, 0.f), ihf);
        bool valid = (x2 - x1 >= 16.f) && (y2 - y1 >= 16.f);
        g_roi[(size_t)n*NANCH + j] = make_float4(x1, y1, x2, y2);
        unsigned int sk = valid ? (__float_as_uint(fg) | 0x80000000u) : 0x007FFFFFu;
        g_keys[((size_t)n << 16) + j] =
            ((unsigned long long)sk << 32) | (unsigned long long)(0xFFFFFFFFu - (unsigned int)j);
    }
}

// ---------------- sorting (bitonic, descending, 64-bit keys) ----------------
__global__ void pad_keys() {
    int t = blockIdx.x * blockDim.x + threadIdx.x;          // 8*28672
    if (t >= NB * (NSORT - NANCH)) return;
    int n = t / (NSORT - NANCH);
    int j = NANCH + t % (NSORT - NANCH);
    g_keys[((size_t)n << 16) + j] = 0ull;
}

__global__ void __launch_bounds__(256) sort_local_full() {
    __shared__ unsigned long long s[4096];
    const int base = blockIdx.x * 4096;
    const int seg  = base & (NSORT - 1);
    for (int i = threadIdx.x; i < 4096; i += 256) s[i] = g_keys[base + i];
    __syncthreads();
    for (int k = 2; k <= 4096; k <<= 1) {
        for (int j = k >> 1; j > 0; j >>= 1) {
            for (int t = threadIdx.x; t < 2048; t += 256) {
                int i = ((t & ~(j-1)) << 1) | (t & (j-1));
                bool desc = (((seg + i) & k) == 0);
                unsigned long long a = s[i], b = s[i | j];
                if ((a < b) == desc) { s[i] = b; s[i | j] = a; }
            }
            __syncthreads();
        }
    }
    for (int i = threadIdx.x; i < 4096; i += 256) g_keys[base + i] = s[i];
}

__global__ void sort_global_step(int k, int j) {
    int t = blockIdx.x * blockDim.x + threadIdx.x;          // 8 * 32768
    int img = t >> 15, ti = t & 32767;
    int i = ((ti & ~(j-1)) << 1) | (ti & (j-1));
    bool desc = ((i & k) == 0);
    size_t p = ((size_t)img << 16) + i;
    unsigned long long a = g_keys[p], b = g_keys[p + j];
    if ((a < b) == desc) { g_keys[p] = b; g_keys[p + j] = a; }
}

__global__ void __launch_bounds__(256) sort_local_finish(int k) {
    __shared__ unsigned long long s[4096];
    const int base = blockIdx.x * 4096;
    const int seg  = base & (NSORT - 1);
    for (int i = threadIdx.x; i < 4096; i += 256) s[i] = g_keys[base + i];
    __syncthreads();
    for (int j = 2048; j > 0; j >>= 1) {
        for (int t = threadIdx.x; t < 2048; t += 256) {
            int i = ((t & ~(j-1)) << 1) | (t & (j-1));
            bool desc = (((seg + i) & k) == 0);
            unsigned long long a = s[i], b = s[i | j];
            if ((a < b) == desc) { s[i] = b; s[i | j] = a; }
        }
        __syncthreads();
    }
    for (int i = threadIdx.x; i < 4096; i += 256) g_keys[base + i] = s[i];
}

// ---------------- NMS ----------------
__global__ void gather_top() {
    const int n = blockIdx.x;
    __shared__ unsigned char sval[3008];
    for (int i = threadIdx.x; i < 3008; i += 128) {
        unsigned long long kk = g_keys[((size_t)n << 16) + i];
        unsigned int sk = (unsigned int)(kk >> 32);
        bool valid = (i < NPRE) && (sk > 0x007FFFFFu);
        float4 bx = make_float4(0.f, 0.f, 0.f, 0.f);
        if (valid) {
            unsigned int j = 0xFFFFFFFFu - (unsigned int)kk;
            bx = g_roi[(size_t)n*NANCH + j];
        }
        g_topbox[(size_t)n*3008 + i] = bx;
        sval[i] = valid ? 1 : 0;
    }
    __syncthreads();
    for (int w = threadIdx.x; w < WPR; w += 128) {
        unsigned long long m = 0ull;
        for (int b = 0; b < 64; ++b) {
            int i = w*64 + b;
            if (i < 3008 && sval[i]) m |= (1ull << b);
        }
        g_vmask[(size_t)n*WPR + w] = m;
    }
}

__global__ void __launch_bounds__(256) build_mask() {
    __shared__ float4 sb[NPRE];
    const int n  = blockIdx.y;
    const int r0 = blockIdx.x * 64;
    for (int i = threadIdx.x; i < NPRE; i += 256) sb[i] = g_topbox[(size_t)n*3008 + i];
    __syncthreads();
    for (int t = threadIdx.x; t < 64*WPR; t += 256) {
        int r = r0 + t / WPR;
        int wj = t % WPR;
        if (r >= NPRE) continue;
        float4 a = sb[r];
        float ar = (a.z - a.x) * (a.w - a.y);
        unsigned long long m = 0ull;
#pragma unroll 4
        for (int b = 0; b < 64; ++b) {
            int j = wj*64 + b;
            if (j >= NPRE || j <= r) continue;
            float4 c = sb[j];
            float xx1 = fmaxf(a.x, c.x), yy1 = fmaxf(a.y, c.y);
            float xx2 = fminf(a.z, c.z), yy2 = fminf(a.w, c.w);
            float inter = fmaxf(xx2 - xx1, 0.f) * fmaxf(yy2 - yy1, 0.f);
            float ac = (c.z - c.x) * (c.w - c.y);
            float iou = inter / (ar + ac - inter + 1e-10f);
            if (iou > 0.7f) m |= (1ull << b);
        }
        g_mask[((size_t)n*NPRE + r)*WPR + wj] = m;
    }
}

__global__ void __launch_bounds__(32) nms_scan(float* __restrict__ out) {
    const int n = blockIdx.x;
    const int lane = threadIdx.x;
    __shared__ unsigned long long srow[64*WPR];
    unsigned long long R0 = ~g_vmask[(size_t)n*WPR + lane];
    unsigned long long R1 = (lane < 15) ? ~g_vmask[(size_t)n*WPR + 32 + lane] : ~0ull;
    int cnt = 0;
    const unsigned long long* mbase = &g_mask[(size_t)n*NPRE*WPR];
    const float* tb = (const float*)g_topbox;
    float* orow = out + OFF_ROIS + (size_t)n*NPOST*4;

    for (int c = 0; c < 47; ++c) {
        int r0 = c * 64;
        int nr = min(64, NPRE - r0);
        for (int idx = lane; idx < nr*WPR; idx += 32)
            srow[idx] = mbase[(size_t)r0*WPR + idx];
        __syncwarp();
        for (int ii = 0; ii < nr; ++ii) {
            int i = r0 + ii;
            unsigned long long m0 = srow[ii*WPR + lane];
            unsigned long long m1 = (lane < 15) ? srow[ii*WPR + 32 + lane] : 0ull;
            int w = i >> 6, b = i & 63;
            unsigned long long own = (w < 32) ? R0 : R1;
            unsigned long long v = __shfl_sync(0xFFFFFFFFu, own, w & 31);
            if (!((v >> b) & 1ull)) {
                R0 |= m0; R1 |= m1;
                if (cnt < NPOST && lane < 4)
                    orow[(size_t)cnt*4 + lane] = tb[((size_t)n*3008 + i)*4 + lane];
                ++cnt;
            }
        }
        __syncwarp();
    }
    for (int z = cnt*4 + lane; z < NPOST*4; z += 32) orow[z] = 0.f;
}

__global__ void write_misc(float* __restrict__ out) {
    int i = blockIdx.x * blockDim.x + threadIdx.x;
    if (i < NB * NPOST) out[OFF_RIDX + i] = (float)(i / NPOST);
}

// diagnostic no-op: shifts launch index so ncu profiles the conv (idx 4)
__global__ void noop_k() {}

// ---------------- launch ----------------
extern "C" void kernel_launch(void* const* d_in, const int* in_sizes, int n_in,
                              void* d_out, int out_size)
{
    const float* x   = (const float*)d_in[0];
    const int*   imh = (const int*)d_in[1];
    const int*   imw = (const int*)d_in[2];
    const float* w1  = (const float*)d_in[3];
    const float* b1  = (const float*)d_in[4];
    const float* sw  = (const float*)d_in[5];
    const float* sbp = (const float*)d_in[6];
    const float* lw  = (const float*)d_in[7];
    const float* lbp = (const float*)d_in[8];
    float* out = (float*)d_out;

    static int smem_set = 0;
    if (!smem_set) {
        cudaFuncSetAttribute(conv3x3_relu,
            cudaFuncAttributeMaxDynamicSharedMemorySize, 2*(XS_ELEMS+WS_ELEMS)*4);
        smem_set = 1;
    }

    // conv is launch idx 4 — where the profiler window landed last round
    pad_input<<<(int)(((size_t)NB*CIN*XPLANE + 255)/256), 256>>>(x);
    transpose_w<<<(CIN*9*CIN + 255)/256, 256>>>(w1);
    pad_keys<<<(NB*(NSORT-NANCH) + 255)/256, 256>>>();
    noop_k<<<1, 32>>>();
    conv3x3_relu<<<dim3(16, 8, 8), 256, 2*(XS_ELEMS+WS_ELEMS)*4>>>(b1);
    heads_proposal<<<dim3(16, 8), 256>>>(sw, sbp, lw, lbp, imh, imw, out);
    sort_local_full<<<128, 256>>>();
    for (int k = 8192; k <= 65536; k <<= 1) {
        for (int j = k >> 1; j >= 4096; j >>= 1)
            sort_global_step<<<1024, 256>>>(k, j);
        sort_local_finish<<<128, 256>>>(k);
    }
    gather_top<<<8, 128>>>();
    build_mask<<<dim3(47, 8), 256>>>();
    nms_scan<<<8, 32>>>(out);
    write_misc<<<19, 256>>>(out);
}